// round 7
// baseline (speedup 1.0000x reference)
#include <cuda_runtime.h>
#include <cuda_bf16.h>

// Problem dims (fixed by the reference)
#define BB   8
#define TT   4096
#define CC   256
#define NC   64           // chunks along T for the parallel WKV scan
#define LCH  (TT / NC)    // 64 steps per chunk
#define INV_T (1.0f / 4096.0f)
#define INV_C (1.0f / 256.0f)

// ---------------- scratch (static __device__ — no allocations allowed) -----
__device__ float g_k [BB * TT * CC];   // 128 MB
__device__ float g_v [BB * TT * CC];   // 128 MB
__device__ float g_sr[BB * TT * CC];   // sigmoid(r); overwritten in-place with z = sr*LN(y)
__device__ float g_rp[BB * NC * CC];   // chunk residuals (p,q,o)
__device__ float g_rq[BB * NC * CC];
__device__ float g_ro[BB * NC * CC];
__device__ float g_pp[BB * NC * CC];   // chunk-prefix states
__device__ float g_pq[BB * NC * CC];
__device__ float g_po[BB * NC * CC];

// ---------------------------------------------------------------------------
// GEMM (NT): O[m,n] = sum_c A[m,c] * W[n,c].  64x64 tile, BK=16, 256 threads,
// 4x4 per thread.  Fused k/v/r variant: grid.x = n_tile(4) * weight(3), with
// weight in the upper bits so 12 consecutive blocks share one A m-tile (L2).
// ---------------------------------------------------------------------------
__device__ __forceinline__ void gemm_tile_body(
    const float* __restrict__ A, const float* __restrict__ W,
    int m0, int n0, float acc[4][4])
{
    __shared__ float As[16][68];
    __shared__ float Ws[16][68];
    const int tid = threadIdx.x;
    const int lr  = tid >> 2;          // 0..63 : row within tile
    const int lk  = (tid & 3) << 2;    // 0,4,8,12 : k-offset (float4)
    const int tr  = tid >> 4;          // 0..15
    const int tc  = tid & 15;          // 0..15

    const float* Arow = A + (m0 + lr) * CC + lk;
    const float* Wrow = W + (n0 + lr) * CC + lk;

    for (int kb = 0; kb < CC; kb += 16) {
        float4 av = *(const float4*)(Arow + kb);
        float4 wv = *(const float4*)(Wrow + kb);
        __syncthreads();
        As[lk + 0][lr] = av.x; As[lk + 1][lr] = av.y;
        As[lk + 2][lr] = av.z; As[lk + 3][lr] = av.w;
        Ws[lk + 0][lr] = wv.x; Ws[lk + 1][lr] = wv.y;
        Ws[lk + 2][lr] = wv.z; Ws[lk + 3][lr] = wv.w;
        __syncthreads();
#pragma unroll
        for (int kk = 0; kk < 16; kk++) {
            float4 a = *(const float4*)&As[kk][tr << 2];
            float4 b = *(const float4*)&Ws[kk][tc << 2];
            acc[0][0] += a.x * b.x; acc[0][1] += a.x * b.y; acc[0][2] += a.x * b.z; acc[0][3] += a.x * b.w;
            acc[1][0] += a.y * b.x; acc[1][1] += a.y * b.y; acc[1][2] += a.y * b.z; acc[1][3] += a.y * b.w;
            acc[2][0] += a.z * b.x; acc[2][1] += a.z * b.y; acc[2][2] += a.z * b.z; acc[2][3] += a.z * b.w;
            acc[3][0] += a.w * b.x; acc[3][1] += a.w * b.y; acc[3][2] += a.w * b.z; acc[3][3] += a.w * b.w;
        }
    }
}

__global__ __launch_bounds__(256)
void gemm_kvr_kernel(const float* __restrict__ x,
                     const float* __restrict__ Wk,
                     const float* __restrict__ Wv,
                     const float* __restrict__ Wr)
{
    const int n_tile = blockIdx.x & 3;
    const int w_id   = blockIdx.x >> 2;       // 0:k 1:v 2:r
    const int m0     = blockIdx.y * 64;
    const int n0     = n_tile * 64;
    const float* W = (w_id == 0) ? Wk : (w_id == 1) ? Wv : Wr;
    float*       O = (w_id == 0) ? g_k : (w_id == 1) ? g_v : g_sr;

    float acc[4][4] = {};
    gemm_tile_body(x, W, m0, n0, acc);

    const int tr = threadIdx.x >> 4, tc = threadIdx.x & 15;
    float* Out = O + (m0 + (tr << 2)) * CC + n0 + (tc << 2);
#pragma unroll
    for (int i = 0; i < 4; i++) {
        float4 o4;
        float v0 = acc[i][0], v1 = acc[i][1], v2 = acc[i][2], v3 = acc[i][3];
        if (w_id == 2) {  // sigmoid for the r projection
            v0 = __fdividef(1.f, 1.f + __expf(-v0));
            v1 = __fdividef(1.f, 1.f + __expf(-v1));
            v2 = __fdividef(1.f, 1.f + __expf(-v2));
            v3 = __fdividef(1.f, 1.f + __expf(-v3));
        }
        o4.x = v0; o4.y = v1; o4.z = v2; o4.w = v3;
        *(float4*)(Out + i * CC) = o4;
    }
}

__global__ __launch_bounds__(256)
void gemm_out_kernel(const float* __restrict__ Wo, float* __restrict__ out)
{
    const int n0 = (blockIdx.x & 3) * 64;
    const int m0 = blockIdx.y * 64;
    float acc[4][4] = {};
    gemm_tile_body(g_sr, Wo, m0, n0, acc);
    const int tr = threadIdx.x >> 4, tc = threadIdx.x & 15;
    float* Out = out + (m0 + (tr << 2)) * CC + n0 + (tc << 2);
#pragma unroll
    for (int i = 0; i < 4; i++) {
        float4 o4 = { acc[i][0], acc[i][1], acc[i][2], acc[i][3] };
        *(float4*)(Out + i * CC) = o4;
    }
}

// ---------------------------------------------------------------------------
// WKV pass 1: per (b, chunk) run the state recurrence from identity
// (p=0, q=0, o=-1e38) over L steps -> chunk residual (rp, rq, ro).
// One thread per channel: loads over c are fully coalesced.
// ---------------------------------------------------------------------------
__global__ __launch_bounds__(256)
void wkv_pass1_kernel(const float* __restrict__ decay)
{
    const int c = threadIdx.x;
    const int j = blockIdx.x;     // chunk
    const int b = blockIdx.y;
    const float w = decay[c] * INV_T;
    float p = 0.f, q = 0.f, o = -1e38f;
    int idx = (b * TT + j * LCH) * CC + c;
#pragma unroll 4
    for (int t = 0; t < LCH; t++, idx += CC) {
        float kt = g_k[idx], vt = g_v[idx];
        float no = fmaxf(w + o, kt);
        float ea = __expf(w + o - no);
        float eb = __expf(kt - no);
        p = ea * p + eb * vt;
        q = ea * q + eb;
        o = no;
    }
    const int s = (b * NC + j) * CC + c;
    g_rp[s] = p; g_rq[s] = q; g_ro[s] = o;
}

// ---------------------------------------------------------------------------
// WKV pass 2: sequential combine across the NC chunk summaries per (b,c).
// Writes the prefix state at each chunk start. 8 blocks x 256 threads, cheap.
// combine:   o' = max(o + L*w, ro);  p' = e^{o+Lw-o'} p + e^{ro-o'} rp ; q same
// ---------------------------------------------------------------------------
__global__ __launch_bounds__(256)
void wkv_pass2_kernel(const float* __restrict__ decay)
{
    const int c = threadIdx.x;
    const int b = blockIdx.x;
    const float Lw = decay[c] * INV_T * (float)LCH;
    float p = 0.f, q = 0.f, o = -1e38f;
    for (int j = 0; j < NC; j++) {
        const int s = (b * NC + j) * CC + c;
        g_pp[s] = p; g_pq[s] = q; g_po[s] = o;
        float so = o + Lw;
        float ro = g_ro[s], rp = g_rp[s], rq = g_rq[s];
        float no = fmaxf(so, ro);
        float ea = __expf(so - no);
        float eb = __expf(ro - no);
        p = ea * p + eb * rp;
        q = ea * q + eb * rq;
        o = no;
    }
}

// ---------------------------------------------------------------------------
// WKV pass 3: replay each chunk from its prefix state, emit y_t, and FUSE
// LayerNorm over C (the block owns all 256 channels of each t) plus the
// sigmoid gate: writes z = sigmoid(r) * LN(y) in-place into g_sr.
// Double-buffered smem reduction -> one barrier per timestep.
// ---------------------------------------------------------------------------
__global__ __launch_bounds__(256)
void wkv_pass3_kernel(const float* __restrict__ decay,
                      const float* __restrict__ first,
                      const float* __restrict__ ln_w,
                      const float* __restrict__ ln_b)
{
    __shared__ float sh_s [2][8];
    __shared__ float sh_s2[2][8];
    const int c = threadIdx.x;
    const int j = blockIdx.x;
    const int b = blockIdx.y;
    const int wid  = c >> 5;
    const int lane = c & 31;

    const float w = decay[c] * INV_T;
    const float u = first[c] * INV_T;
    const float lw = ln_w[c], lb = ln_b[c];

    const int s = (b * NC + j) * CC + c;
    float p = g_pp[s], q = g_pq[s], o = g_po[s];

    int idx = (b * TT + j * LCH) * CC + c;
    for (int t = 0; t < LCH; t++, idx += CC) {
        float kt = g_k[idx], vt = g_v[idx];

        // output with the 'first' bonus u (uses state BEFORE this step)
        float no = fmaxf(o, u + kt);
        float ea = __expf(o - no);
        float eb = __expf(u + kt - no);
        float y  = __fdividef(ea * p + eb * vt, ea * q + eb);

        // state update
        float no2 = fmaxf(w + o, kt);
        float e2  = __expf(w + o - no2);
        float e3  = __expf(kt - no2);
        p = e2 * p + e3 * vt;
        q = e2 * q + e3;
        o = no2;

        // block LayerNorm over the 256 channels of this timestep
        float sv = y, sv2 = y * y;
#pragma unroll
        for (int off = 16; off; off >>= 1) {
            sv  += __shfl_xor_sync(0xffffffffu, sv,  off);
            sv2 += __shfl_xor_sync(0xffffffffu, sv2, off);
        }
        const int buf = t & 1;
        if (lane == 0) { sh_s[buf][wid] = sv; sh_s2[buf][wid] = sv2; }
        __syncthreads();
        float mean = 0.f, msq = 0.f;
#pragma unroll
        for (int i = 0; i < 8; i++) { mean += sh_s[buf][i]; msq += sh_s2[buf][i]; }
        mean *= INV_C;
        float var = msq * INV_C - mean * mean;
        float inv = rsqrtf(var + 1e-5f);

        float z = (y - mean) * inv * lw + lb;
        g_sr[idx] = z * g_sr[idx];   // in-place: z = sigmoid(r) * LN(y)
    }
}

// ---------------------------------------------------------------------------
extern "C" void kernel_launch(void* const* d_in, const int* in_sizes, int n_in,
                              void* d_out, int out_size)
{
    const float* x     = (const float*)d_in[0];
    const float* Wk    = (const float*)d_in[1];
    const float* Wv    = (const float*)d_in[2];
    const float* Wr    = (const float*)d_in[3];
    const float* Wo    = (const float*)d_in[4];
    const float* decay = (const float*)d_in[5];
    const float* first = (const float*)d_in[6];
    const float* ln_w  = (const float*)d_in[7];
    const float* ln_b  = (const float*)d_in[8];
    float* out = (float*)d_out;

    const int MT = (BB * TT) / 64;   // 512 m-tiles

    gemm_kvr_kernel<<<dim3(12, MT), 256>>>(x, Wk, Wv, Wr);
    wkv_pass1_kernel<<<dim3(NC, BB), 256>>>(decay);
    wkv_pass2_kernel<<<BB, 256>>>(decay);
    wkv_pass3_kernel<<<dim3(NC, BB), 256>>>(decay, first, ln_w, ln_b);
    gemm_out_kernel<<<dim3(4, MT), 256>>>(Wo, out);
}

// round 8
// speedup vs baseline: 1.0005x; 1.0005x over previous
#include <cuda_runtime.h>
#include <cuda_bf16.h>

// Problem dims (fixed by the reference)
#define BB   8
#define TT   4096
#define CC   256
#define NC   64           // chunks along T for the parallel WKV scan
#define LCH  (TT / NC)    // 64 steps per chunk
#define INV_T (1.0f / 4096.0f)
#define INV_C (1.0f / 256.0f)

// ---------------- scratch (static __device__ — no allocations allowed) -----
__device__ float g_k [BB * TT * CC];   // 128 MB
__device__ float g_v [BB * TT * CC];   // 128 MB
__device__ float g_sr[BB * TT * CC];   // sigmoid(r); overwritten in-place with z = sr*LN(y)
__device__ float g_rp[BB * NC * CC];   // chunk residuals (p,q,o)
__device__ float g_rq[BB * NC * CC];
__device__ float g_ro[BB * NC * CC];
__device__ float g_pp[BB * NC * CC];   // chunk-prefix states
__device__ float g_pq[BB * NC * CC];
__device__ float g_po[BB * NC * CC];

// ---------------------------------------------------------------------------
// GEMM (NT): O[m,n] = sum_c A[m,c] * W[n,c].  64x64 tile, BK=16, 256 threads,
// 4x4 per thread.  Fused k/v/r variant: grid.x = n_tile(4) * weight(3), with
// weight in the upper bits so 12 consecutive blocks share one A m-tile (L2).
// ---------------------------------------------------------------------------
__device__ __forceinline__ void gemm_tile_body(
    const float* __restrict__ A, const float* __restrict__ W,
    int m0, int n0, float acc[4][4])
{
    __shared__ float As[16][68];
    __shared__ float Ws[16][68];
    const int tid = threadIdx.x;
    const int lr  = tid >> 2;          // 0..63 : row within tile
    const int lk  = (tid & 3) << 2;    // 0,4,8,12 : k-offset (float4)
    const int tr  = tid >> 4;          // 0..15
    const int tc  = tid & 15;          // 0..15

    const float* Arow = A + (m0 + lr) * CC + lk;
    const float* Wrow = W + (n0 + lr) * CC + lk;

    for (int kb = 0; kb < CC; kb += 16) {
        float4 av = *(const float4*)(Arow + kb);
        float4 wv = *(const float4*)(Wrow + kb);
        __syncthreads();
        As[lk + 0][lr] = av.x; As[lk + 1][lr] = av.y;
        As[lk + 2][lr] = av.z; As[lk + 3][lr] = av.w;
        Ws[lk + 0][lr] = wv.x; Ws[lk + 1][lr] = wv.y;
        Ws[lk + 2][lr] = wv.z; Ws[lk + 3][lr] = wv.w;
        __syncthreads();
#pragma unroll
        for (int kk = 0; kk < 16; kk++) {
            float4 a = *(const float4*)&As[kk][tr << 2];
            float4 b = *(const float4*)&Ws[kk][tc << 2];
            acc[0][0] += a.x * b.x; acc[0][1] += a.x * b.y; acc[0][2] += a.x * b.z; acc[0][3] += a.x * b.w;
            acc[1][0] += a.y * b.x; acc[1][1] += a.y * b.y; acc[1][2] += a.y * b.z; acc[1][3] += a.y * b.w;
            acc[2][0] += a.z * b.x; acc[2][1] += a.z * b.y; acc[2][2] += a.z * b.z; acc[2][3] += a.z * b.w;
            acc[3][0] += a.w * b.x; acc[3][1] += a.w * b.y; acc[3][2] += a.w * b.z; acc[3][3] += a.w * b.w;
        }
    }
}

__global__ __launch_bounds__(256)
void gemm_kvr_kernel(const float* __restrict__ x,
                     const float* __restrict__ Wk,
                     const float* __restrict__ Wv,
                     const float* __restrict__ Wr)
{
    const int n_tile = blockIdx.x & 3;
    const int w_id   = blockIdx.x >> 2;       // 0:k 1:v 2:r
    const int m0     = blockIdx.y * 64;
    const int n0     = n_tile * 64;
    const float* W = (w_id == 0) ? Wk : (w_id == 1) ? Wv : Wr;
    float*       O = (w_id == 0) ? g_k : (w_id == 1) ? g_v : g_sr;

    float acc[4][4] = {};
    gemm_tile_body(x, W, m0, n0, acc);

    const int tr = threadIdx.x >> 4, tc = threadIdx.x & 15;
    float* Out = O + (m0 + (tr << 2)) * CC + n0 + (tc << 2);
#pragma unroll
    for (int i = 0; i < 4; i++) {
        float4 o4;
        float v0 = acc[i][0], v1 = acc[i][1], v2 = acc[i][2], v3 = acc[i][3];
        if (w_id == 2) {  // sigmoid for the r projection
            v0 = __fdividef(1.f, 1.f + __expf(-v0));
            v1 = __fdividef(1.f, 1.f + __expf(-v1));
            v2 = __fdividef(1.f, 1.f + __expf(-v2));
            v3 = __fdividef(1.f, 1.f + __expf(-v3));
        }
        o4.x = v0; o4.y = v1; o4.z = v2; o4.w = v3;
        *(float4*)(Out + i * CC) = o4;
    }
}

__global__ __launch_bounds__(256)
void gemm_out_kernel(const float* __restrict__ Wo, float* __restrict__ out)
{
    const int n0 = (blockIdx.x & 3) * 64;
    const int m0 = blockIdx.y * 64;
    float acc[4][4] = {};
    gemm_tile_body(g_sr, Wo, m0, n0, acc);
    const int tr = threadIdx.x >> 4, tc = threadIdx.x & 15;
    float* Out = out + (m0 + (tr << 2)) * CC + n0 + (tc << 2);
#pragma unroll
    for (int i = 0; i < 4; i++) {
        float4 o4 = { acc[i][0], acc[i][1], acc[i][2], acc[i][3] };
        *(float4*)(Out + i * CC) = o4;
    }
}

// ---------------------------------------------------------------------------
// WKV pass 1: per (b, chunk) run the state recurrence from identity
// (p=0, q=0, o=-1e38) over L steps -> chunk residual (rp, rq, ro).
// One thread per channel: loads over c are fully coalesced.
// ---------------------------------------------------------------------------
__global__ __launch_bounds__(256)
void wkv_pass1_kernel(const float* __restrict__ decay)
{
    const int c = threadIdx.x;
    const int j = blockIdx.x;     // chunk
    const int b = blockIdx.y;
    const float w = decay[c] * INV_T;
    float p = 0.f, q = 0.f, o = -1e38f;
    int idx = (b * TT + j * LCH) * CC + c;
#pragma unroll 4
    for (int t = 0; t < LCH; t++, idx += CC) {
        float kt = g_k[idx], vt = g_v[idx];
        float no = fmaxf(w + o, kt);
        float ea = __expf(w + o - no);
        float eb = __expf(kt - no);
        p = ea * p + eb * vt;
        q = ea * q + eb;
        o = no;
    }
    const int s = (b * NC + j) * CC + c;
    g_rp[s] = p; g_rq[s] = q; g_ro[s] = o;
}

// ---------------------------------------------------------------------------
// WKV pass 2: sequential combine across the NC chunk summaries per (b,c).
// Writes the prefix state at each chunk start. 8 blocks x 256 threads, cheap.
// combine:   o' = max(o + L*w, ro);  p' = e^{o+Lw-o'} p + e^{ro-o'} rp ; q same
// ---------------------------------------------------------------------------
__global__ __launch_bounds__(256)
void wkv_pass2_kernel(const float* __restrict__ decay)
{
    const int c = threadIdx.x;
    const int b = blockIdx.x;
    const float Lw = decay[c] * INV_T * (float)LCH;
    float p = 0.f, q = 0.f, o = -1e38f;
    for (int j = 0; j < NC; j++) {
        const int s = (b * NC + j) * CC + c;
        g_pp[s] = p; g_pq[s] = q; g_po[s] = o;
        float so = o + Lw;
        float ro = g_ro[s], rp = g_rp[s], rq = g_rq[s];
        float no = fmaxf(so, ro);
        float ea = __expf(so - no);
        float eb = __expf(ro - no);
        p = ea * p + eb * rp;
        q = ea * q + eb * rq;
        o = no;
    }
}

// ---------------------------------------------------------------------------
// WKV pass 3: replay each chunk from its prefix state, emit y_t, and FUSE
// LayerNorm over C (the block owns all 256 channels of each t) plus the
// sigmoid gate: writes z = sigmoid(r) * LN(y) in-place into g_sr.
// Double-buffered smem reduction -> one barrier per timestep.
// ---------------------------------------------------------------------------
__global__ __launch_bounds__(256)
void wkv_pass3_kernel(const float* __restrict__ decay,
                      const float* __restrict__ first,
                      const float* __restrict__ ln_w,
                      const float* __restrict__ ln_b)
{
    __shared__ float sh_s [2][8];
    __shared__ float sh_s2[2][8];
    const int c = threadIdx.x;
    const int j = blockIdx.x;
    const int b = blockIdx.y;
    const int wid  = c >> 5;
    const int lane = c & 31;

    const float w = decay[c] * INV_T;
    const float u = first[c] * INV_T;
    const float lw = ln_w[c], lb = ln_b[c];

    const int s = (b * NC + j) * CC + c;
    float p = g_pp[s], q = g_pq[s], o = g_po[s];

    int idx = (b * TT + j * LCH) * CC + c;
    for (int t = 0; t < LCH; t++, idx += CC) {
        float kt = g_k[idx], vt = g_v[idx];

        // output with the 'first' bonus u (uses state BEFORE this step)
        float no = fmaxf(o, u + kt);
        float ea = __expf(o - no);
        float eb = __expf(u + kt - no);
        float y  = __fdividef(ea * p + eb * vt, ea * q + eb);

        // state update
        float no2 = fmaxf(w + o, kt);
        float e2  = __expf(w + o - no2);
        float e3  = __expf(kt - no2);
        p = e2 * p + e3 * vt;
        q = e2 * q + e3;
        o = no2;

        // block LayerNorm over the 256 channels of this timestep
        float sv = y, sv2 = y * y;
#pragma unroll
        for (int off = 16; off; off >>= 1) {
            sv  += __shfl_xor_sync(0xffffffffu, sv,  off);
            sv2 += __shfl_xor_sync(0xffffffffu, sv2, off);
        }
        const int buf = t & 1;
        if (lane == 0) { sh_s[buf][wid] = sv; sh_s2[buf][wid] = sv2; }
        __syncthreads();
        float mean = 0.f, msq = 0.f;
#pragma unroll
        for (int i = 0; i < 8; i++) { mean += sh_s[buf][i]; msq += sh_s2[buf][i]; }
        mean *= INV_C;
        float var = msq * INV_C - mean * mean;
        float inv = rsqrtf(var + 1e-5f);

        float z = (y - mean) * inv * lw + lb;
        g_sr[idx] = z * g_sr[idx];   // in-place: z = sigmoid(r) * LN(y)
    }
}

// ---------------------------------------------------------------------------
extern "C" void kernel_launch(void* const* d_in, const int* in_sizes, int n_in,
                              void* d_out, int out_size)
{
    const float* x     = (const float*)d_in[0];
    const float* Wk    = (const float*)d_in[1];
    const float* Wv    = (const float*)d_in[2];
    const float* Wr    = (const float*)d_in[3];
    const float* Wo    = (const float*)d_in[4];
    const float* decay = (const float*)d_in[5];
    const float* first = (const float*)d_in[6];
    const float* ln_w  = (const float*)d_in[7];
    const float* ln_b  = (const float*)d_in[8];
    float* out = (float*)d_out;

    const int MT = (BB * TT) / 64;   // 512 m-tiles

    gemm_kvr_kernel<<<dim3(12, MT), 256>>>(x, Wk, Wv, Wr);
    wkv_pass1_kernel<<<dim3(NC, BB), 256>>>(decay);
    wkv_pass2_kernel<<<BB, 256>>>(decay);
    wkv_pass3_kernel<<<dim3(NC, BB), 256>>>(decay, first, ln_w, ln_b);
    gemm_out_kernel<<<dim3(4, MT), 256>>>(Wo, out);
}

// round 10
// speedup vs baseline: 1.7190x; 1.7180x over previous
#include <cuda_runtime.h>
#include <cuda_bf16.h>
#include <cstdint>

// Problem dims (fixed by the reference)
#define BB   8
#define TT   4096
#define CC   256
#define NC   64           // chunks along T for the parallel WKV scan
#define LCH  (TT / NC)    // 64 steps per chunk
#define INV_T (1.0f / 4096.0f)
#define INV_C (1.0f / 256.0f)

// ---------------- scratch (static __device__ — no allocations allowed) -----
__device__ float g_k [BB * TT * CC];
__device__ float g_v [BB * TT * CC];
__device__ float g_sr[BB * TT * CC];   // sigmoid(r); later overwritten with z = sr*LN(y)
__device__ float g_rp[BB * NC * CC];
__device__ float g_rq[BB * NC * CC];
__device__ float g_ro[BB * NC * CC];
__device__ float g_pp[BB * NC * CC];
__device__ float g_pq[BB * NC * CC];
__device__ float g_po[BB * NC * CC];

// bf16 hi/lo split weights, [w][n=256][k=256] row-major, packed as uint32 (2 bf16)
__device__ uint32_t g_whi[4 * 256 * 128];   // 512 KB
__device__ uint32_t g_wlo[4 * 256 * 128];   // 512 KB

// ---------------------------------------------------------------------------
// helpers
// ---------------------------------------------------------------------------
__device__ __forceinline__ uint32_t smem_u32(const void* p) {
    uint32_t a;
    asm("{ .reg .u64 t; cvta.to.shared.u64 t, %1; cvt.u32.u64 %0, t; }"
        : "=r"(a) : "l"(p));
    return a;
}

// split a pair of fp32 into packed bf16 hi and bf16 lo words
__device__ __forceinline__ void split2(float a, float b, uint32_t& h, uint32_t& l) {
    __nv_bfloat16 ha = __float2bfloat16_rn(a);
    __nv_bfloat16 hb = __float2bfloat16_rn(b);
    __nv_bfloat16 la = __float2bfloat16_rn(a - __bfloat162float(ha));
    __nv_bfloat16 lb = __float2bfloat16_rn(b - __bfloat162float(hb));
    h = ((uint32_t)__bfloat16_as_ushort(hb) << 16) | __bfloat16_as_ushort(ha);
    l = ((uint32_t)__bfloat16_as_ushort(lb) << 16) | __bfloat16_as_ushort(la);
}

__device__ __forceinline__ void ldmx4(uint32_t* r, uint32_t addr) {
    asm volatile("ldmatrix.sync.aligned.m8n8.x4.shared.b16 {%0,%1,%2,%3}, [%4];"
                 : "=r"(r[0]), "=r"(r[1]), "=r"(r[2]), "=r"(r[3]) : "r"(addr));
}
__device__ __forceinline__ void ldmx2(uint32_t* r, uint32_t addr) {
    asm volatile("ldmatrix.sync.aligned.m8n8.x2.shared.b16 {%0,%1}, [%2];"
                 : "=r"(r[0]), "=r"(r[1]) : "r"(addr));
}
__device__ __forceinline__ void mma16816(float* d, const uint32_t* a, const uint32_t* b) {
    asm volatile(
        "mma.sync.aligned.m16n8k16.row.col.f32.bf16.bf16.f32 "
        "{%0,%1,%2,%3}, {%4,%5,%6,%7}, {%8,%9}, {%0,%1,%2,%3};"
        : "+f"(d[0]), "+f"(d[1]), "+f"(d[2]), "+f"(d[3])
        : "r"(a[0]), "r"(a[1]), "r"(a[2]), "r"(a[3]), "r"(b[0]), "r"(b[1]));
}

// ---------------------------------------------------------------------------
// Weight prep: fp32 [256,256] -> bf16 hi/lo packed pairs at [w][n][k/2]
// ---------------------------------------------------------------------------
__global__ __launch_bounds__(256)
void prep_w_kernel(const float* __restrict__ Wk, const float* __restrict__ Wv,
                   const float* __restrict__ Wr, const float* __restrict__ Wo)
{
    int gid = blockIdx.x * 256 + threadIdx.x;    // 0 .. 131071 = 4*256*128
    int kp  = gid & 127;                         // k-pair
    int n   = (gid >> 7) & 255;
    int w   = gid >> 15;
    const float* W = (w == 0) ? Wk : (w == 1) ? Wv : (w == 2) ? Wr : Wo;
    float2 v = *(const float2*)(W + n * 256 + kp * 2);
    uint32_t h, l;
    split2(v.x, v.y, h, l);
    g_whi[gid] = h;
    g_wlo[gid] = l;
}

// ---------------------------------------------------------------------------
// Split-bf16 tensor-core GEMM (NT) via ldmatrix + mma.sync (compute_103-legal).
// O[m,n] = sum_c A[m,c] * W[n,c].  CTA tile 128x128, BK=32, 8 warps (2m x 4n),
// warp tile 64x32, fp32 accum. 3 MMA terms: Ahi*Whi + Ahi*Wlo + Alo*Whi.
// ---------------------------------------------------------------------------
#define PITCH 80   // smem row pitch in bytes: 32 bf16 (64 B) + 16 B pad

__device__ __forceinline__ void gemm_mma_body(
    const float* __restrict__ A, int w_sel, float* __restrict__ O,
    int m0, int n0, int do_sig)
{
    __shared__ __align__(16) unsigned char sAhi[128 * PITCH];
    __shared__ __align__(16) unsigned char sAlo[128 * PITCH];
    __shared__ __align__(16) unsigned char sWhi[128 * PITCH];
    __shared__ __align__(16) unsigned char sWlo[128 * PITCH];

    const int tid  = threadIdx.x;
    const int wid  = tid >> 5;
    const int lane = tid & 31;
    const int wm   = wid & 1;        // 0..1 : 64-row half
    const int wn   = wid >> 1;       // 0..3 : 32-col quarter

    const uint32_t uAhi = smem_u32(sAhi);
    const uint32_t uAlo = smem_u32(sAlo);
    const uint32_t uWhi = smem_u32(sWhi);
    const uint32_t uWlo = smem_u32(sWlo);

    // ldmatrix per-lane addresses (byte offsets inside a tile)
    // A x4: lanes 0-7 rows0-7/k0, 8-15 rows8-15/k0, 16-23 rows0-7/k8, 24-31 rows8-15/k8
    const uint32_t aOff = (uint32_t)((wm * 64 + (lane & 15)) * PITCH + (lane >> 4) * 16);
    // B x2: lanes 0-7 rows n..n+7/k0, 8-15 same rows /k8 (lanes 16-31 ignored)
    const uint32_t bOff = (uint32_t)((wn * 32 + (lane & 7)) * PITCH + ((lane >> 3) & 1) * 16);

    float acc[4][4][4];
#pragma unroll
    for (int i = 0; i < 4; i++)
#pragma unroll
        for (int j = 0; j < 4; j++)
#pragma unroll
            for (int e = 0; e < 4; e++) acc[i][j][e] = 0.f;

    const int arow = tid >> 1;          // staging: each thread owns half a row
    const int ahalf = tid & 1;          // 16 floats

    for (int kc = 0; kc < 8; kc++) {    // K chunks of 32
        __syncthreads();
        // --- stage A chunk: fp32 -> bf16 hi/lo ---
        {
            const float* Ar = A + (size_t)(m0 + arow) * CC + kc * 32 + ahalf * 16;
            uint32_t h[8], l[8];
#pragma unroll
            for (int q = 0; q < 4; q++) {
                float4 f = *(const float4*)(Ar + q * 4);
                split2(f.x, f.y, h[q * 2],     l[q * 2]);
                split2(f.z, f.w, h[q * 2 + 1], l[q * 2 + 1]);
            }
            uint4* dh = (uint4*)(sAhi + arow * PITCH + ahalf * 32);
            uint4* dl = (uint4*)(sAlo + arow * PITCH + ahalf * 32);
            dh[0] = make_uint4(h[0], h[1], h[2], h[3]);
            dh[1] = make_uint4(h[4], h[5], h[6], h[7]);
            dl[0] = make_uint4(l[0], l[1], l[2], l[3]);
            dl[1] = make_uint4(l[4], l[5], l[6], l[7]);
        }
        // --- stage W chunk: pre-split global bf16 straight copy ---
        {
            const int base = ((w_sel * 256 + n0 + arow) * 128 + kc * 16) >> 2;  // uint4 idx
            const uint4* sh = (const uint4*)g_whi + base + ahalf * 2;
            const uint4* sl = (const uint4*)g_wlo + base + ahalf * 2;
            uint4* dh = (uint4*)(sWhi + arow * PITCH + ahalf * 32);
            uint4* dl = (uint4*)(sWlo + arow * PITCH + ahalf * 32);
            dh[0] = sh[0]; dh[1] = sh[1];
            dl[0] = sl[0]; dl[1] = sl[1];
        }
        __syncthreads();

        // --- MMA phase ---
#pragma unroll
        for (int kk = 0; kk < 2; kk++) {
            uint32_t bh[4][2], bl[4][2];
#pragma unroll
            for (int j = 0; j < 4; j++) {
                uint32_t off = bOff + (uint32_t)(j * 8 * PITCH + kk * 32);
                ldmx2(bh[j], uWhi + off);
                ldmx2(bl[j], uWlo + off);
            }
#pragma unroll
            for (int i = 0; i < 4; i++) {
                uint32_t off = aOff + (uint32_t)(i * 16 * PITCH + kk * 32);
                uint32_t ah[4], al[4];
                ldmx4(ah, uAhi + off);
                ldmx4(al, uAlo + off);
#pragma unroll
                for (int j = 0; j < 4; j++) {
                    mma16816(acc[i][j], ah, bh[j]);
                    mma16816(acc[i][j], ah, bl[j]);
                    mma16816(acc[i][j], al, bh[j]);
                }
            }
        }
    }

    // --- epilogue: fragments -> global fp32 ---
    const int r0 = m0 + wm * 64 + (lane >> 2);
    const int c0 = n0 + wn * 32 + (lane & 3) * 2;
#pragma unroll
    for (int i = 0; i < 4; i++) {
#pragma unroll
        for (int j = 0; j < 4; j++) {
            float v0 = acc[i][j][0], v1 = acc[i][j][1];
            float v2 = acc[i][j][2], v3 = acc[i][j][3];
            if (do_sig) {
                v0 = __fdividef(1.f, 1.f + __expf(-v0));
                v1 = __fdividef(1.f, 1.f + __expf(-v1));
                v2 = __fdividef(1.f, 1.f + __expf(-v2));
                v3 = __fdividef(1.f, 1.f + __expf(-v3));
            }
            float* p = O + (size_t)(r0 + i * 16) * CC + c0 + j * 8;
            *(float2*)p              = make_float2(v0, v1);
            *(float2*)(p + 8 * CC)   = make_float2(v2, v3);
        }
    }
}

__global__ __launch_bounds__(256)
void gemm_kvr_mma(const float* __restrict__ x)
{
    const int w     = blockIdx.x >> 1;        // 0:k 1:v 2:r  (x fastest -> share m-tile in L2)
    const int ntile = blockIdx.x & 1;
    float* O = (w == 0) ? g_k : (w == 1) ? g_v : g_sr;
    gemm_mma_body(x, w, O, blockIdx.y * 128, ntile * 128, w == 2);
}

__global__ __launch_bounds__(256)
void gemm_out_mma(float* __restrict__ out)
{
    gemm_mma_body(g_sr, 3, out, blockIdx.y * 128, (blockIdx.x & 1) * 128, 0);
}

// ---------------------------------------------------------------------------
// WKV pass 1: per (b, chunk) run the state recurrence from identity.
// ---------------------------------------------------------------------------
__global__ __launch_bounds__(256)
void wkv_pass1_kernel(const float* __restrict__ decay)
{
    const int c = threadIdx.x;
    const int j = blockIdx.x;
    const int b = blockIdx.y;
    const float w = decay[c] * INV_T;
    float p = 0.f, q = 0.f, o = -1e38f;
    int idx = (b * TT + j * LCH) * CC + c;
#pragma unroll 4
    for (int t = 0; t < LCH; t++, idx += CC) {
        float kt = g_k[idx], vt = g_v[idx];
        float no = fmaxf(w + o, kt);
        float ea = __expf(w + o - no);
        float eb = __expf(kt - no);
        p = ea * p + eb * vt;
        q = ea * q + eb;
        o = no;
    }
    const int s = (b * NC + j) * CC + c;
    g_rp[s] = p; g_rq[s] = q; g_ro[s] = o;
}

// ---------------------------------------------------------------------------
// WKV pass 2: sequential combine across chunk summaries per (b,c).
// ---------------------------------------------------------------------------
__global__ __launch_bounds__(256)
void wkv_pass2_kernel(const float* __restrict__ decay)
{
    const int c = threadIdx.x;
    const int b = blockIdx.x;
    const float Lw = decay[c] * INV_T * (float)LCH;
    float p = 0.f, q = 0.f, o = -1e38f;
    for (int j = 0; j < NC; j++) {
        const int s = (b * NC + j) * CC + c;
        g_pp[s] = p; g_pq[s] = q; g_po[s] = o;
        float so = o + Lw;
        float ro = g_ro[s], rp = g_rp[s], rq = g_rq[s];
        float no = fmaxf(so, ro);
        float ea = __expf(so - no);
        float eb = __expf(ro - no);
        p = ea * p + eb * rp;
        q = ea * q + eb * rq;
        o = no;
    }
}

// ---------------------------------------------------------------------------
// WKV pass 3: replay chunk from prefix state, fuse LayerNorm + sigmoid gate.
// Writes z = sigmoid(r) * LN(y) in-place into g_sr.
// ---------------------------------------------------------------------------
__global__ __launch_bounds__(256)
void wkv_pass3_kernel(const float* __restrict__ decay,
                      const float* __restrict__ first,
                      const float* __restrict__ ln_w,
                      const float* __restrict__ ln_b)
{
    __shared__ float sh_s [2][8];
    __shared__ float sh_s2[2][8];
    const int c = threadIdx.x;
    const int j = blockIdx.x;
    const int b = blockIdx.y;
    const int wid  = c >> 5;
    const int lane = c & 31;

    const float w = decay[c] * INV_T;
    const float u = first[c] * INV_T;
    const float lw = ln_w[c], lb = ln_b[c];

    const int s = (b * NC + j) * CC + c;
    float p = g_pp[s], q = g_pq[s], o = g_po[s];

    int idx = (b * TT + j * LCH) * CC + c;
    for (int t = 0; t < LCH; t++, idx += CC) {
        float kt = g_k[idx], vt = g_v[idx];

        float no = fmaxf(o, u + kt);
        float ea = __expf(o - no);
        float eb = __expf(u + kt - no);
        float y  = __fdividef(ea * p + eb * vt, ea * q + eb);

        float no2 = fmaxf(w + o, kt);
        float e2  = __expf(w + o - no2);
        float e3  = __expf(kt - no2);
        p = e2 * p + e3 * vt;
        q = e2 * q + e3;
        o = no2;

        float sv = y, sv2 = y * y;
#pragma unroll
        for (int off = 16; off; off >>= 1) {
            sv  += __shfl_xor_sync(0xffffffffu, sv,  off);
            sv2 += __shfl_xor_sync(0xffffffffu, sv2, off);
        }
        const int buf = t & 1;
        if (lane == 0) { sh_s[buf][wid] = sv; sh_s2[buf][wid] = sv2; }
        __syncthreads();
        float mean = 0.f, msq = 0.f;
#pragma unroll
        for (int i = 0; i < 8; i++) { mean += sh_s[buf][i]; msq += sh_s2[buf][i]; }
        mean *= INV_C;
        float var = msq * INV_C - mean * mean;
        float inv = rsqrtf(var + 1e-5f);

        float z = (y - mean) * inv * lw + lb;
        g_sr[idx] = z * g_sr[idx];
    }
}

// ---------------------------------------------------------------------------
extern "C" void kernel_launch(void* const* d_in, const int* in_sizes, int n_in,
                              void* d_out, int out_size)
{
    const float* x     = (const float*)d_in[0];
    const float* Wk    = (const float*)d_in[1];
    const float* Wv    = (const float*)d_in[2];
    const float* Wr    = (const float*)d_in[3];
    const float* Wo    = (const float*)d_in[4];
    const float* decay = (const float*)d_in[5];
    const float* first = (const float*)d_in[6];
    const float* ln_w  = (const float*)d_in[7];
    const float* ln_b  = (const float*)d_in[8];
    float* out = (float*)d_out;

    const int MT = (BB * TT) / 128;   // 256 m-tiles

    prep_w_kernel<<<512, 256>>>(Wk, Wv, Wr, Wo);
    gemm_kvr_mma<<<dim3(6, MT), 256>>>(x);
    wkv_pass1_kernel<<<dim3(NC, BB), 256>>>(decay);
    wkv_pass2_kernel<<<BB, 256>>>(decay);
    wkv_pass3_kernel<<<dim3(NC, BB), 256>>>(decay, first, ln_w, ln_b);
    gemm_out_mma<<<dim3(2, MT), 256>>>(out);
}

// round 11
// speedup vs baseline: 1.8978x; 1.1040x over previous
#include <cuda_runtime.h>
#include <cuda_bf16.h>
#include <cstdint>

// Problem dims (fixed by the reference)
#define BB   8
#define TT   4096
#define CC   256
#define NC   64           // chunks along T for the parallel WKV scan
#define LCH  (TT / NC)    // 64 steps per chunk
#define INV_T (1.0f / 4096.0f)
#define INV_C (1.0f / 256.0f)

// ---------------- scratch (static __device__ — no allocations allowed) -----
__device__ float g_k [BB * TT * CC];
__device__ float g_v [BB * TT * CC];
__device__ float g_sr[BB * TT * CC];   // sigmoid(r); later overwritten with z = sr*LN(y)
__device__ float g_rp[BB * NC * CC];
__device__ float g_rq[BB * NC * CC];
__device__ float g_ro[BB * NC * CC];
__device__ float g_pp[BB * NC * CC];
__device__ float g_pq[BB * NC * CC];
__device__ float g_po[BB * NC * CC];

// bf16 hi/lo split weights, [w][n=256][k=256] row-major, packed as uint32 (2 bf16)
__device__ uint32_t g_whi[4 * 256 * 128];   // 512 KB
__device__ uint32_t g_wlo[4 * 256 * 128];   // 512 KB

// ---------------------------------------------------------------------------
// helpers
// ---------------------------------------------------------------------------
__device__ __forceinline__ uint32_t smem_u32(const void* p) {
    uint32_t a;
    asm("{ .reg .u64 t; cvta.to.shared.u64 t, %1; cvt.u32.u64 %0, t; }"
        : "=r"(a) : "l"(p));
    return a;
}

// split a pair of fp32 into packed bf16 hi and bf16 lo words
__device__ __forceinline__ void split2(float a, float b, uint32_t& h, uint32_t& l) {
    __nv_bfloat16 ha = __float2bfloat16_rn(a);
    __nv_bfloat16 hb = __float2bfloat16_rn(b);
    __nv_bfloat16 la = __float2bfloat16_rn(a - __bfloat162float(ha));
    __nv_bfloat16 lb = __float2bfloat16_rn(b - __bfloat162float(hb));
    h = ((uint32_t)__bfloat16_as_ushort(hb) << 16) | __bfloat16_as_ushort(ha);
    l = ((uint32_t)__bfloat16_as_ushort(lb) << 16) | __bfloat16_as_ushort(la);
}

__device__ __forceinline__ void ldmx4(uint32_t* r, uint32_t addr) {
    asm volatile("ldmatrix.sync.aligned.m8n8.x4.shared.b16 {%0,%1,%2,%3}, [%4];"
                 : "=r"(r[0]), "=r"(r[1]), "=r"(r[2]), "=r"(r[3]) : "r"(addr));
}
__device__ __forceinline__ void ldmx2(uint32_t* r, uint32_t addr) {
    asm volatile("ldmatrix.sync.aligned.m8n8.x2.shared.b16 {%0,%1}, [%2];"
                 : "=r"(r[0]), "=r"(r[1]) : "r"(addr));
}
__device__ __forceinline__ void mma16816(float* d, const uint32_t* a, const uint32_t* b) {
    asm volatile(
        "mma.sync.aligned.m16n8k16.row.col.f32.bf16.bf16.f32 "
        "{%0,%1,%2,%3}, {%4,%5,%6,%7}, {%8,%9}, {%0,%1,%2,%3};"
        : "+f"(d[0]), "+f"(d[1]), "+f"(d[2]), "+f"(d[3])
        : "r"(a[0]), "r"(a[1]), "r"(a[2]), "r"(a[3]), "r"(b[0]), "r"(b[1]));
}

// ---------------------------------------------------------------------------
// Weight prep: fp32 [256,256] -> bf16 hi/lo packed pairs at [w][n][k/2]
// ---------------------------------------------------------------------------
__global__ __launch_bounds__(256)
void prep_w_kernel(const float* __restrict__ Wk, const float* __restrict__ Wv,
                   const float* __restrict__ Wr, const float* __restrict__ Wo)
{
    int gid = blockIdx.x * 256 + threadIdx.x;    // 0 .. 131071 = 4*256*128
    int kp  = gid & 127;                         // k-pair
    int n   = (gid >> 7) & 255;
    int w   = gid >> 15;
    const float* W = (w == 0) ? Wk : (w == 1) ? Wv : (w == 2) ? Wr : Wo;
    float2 v = *(const float2*)(W + n * 256 + kp * 2);
    uint32_t h, l;
    split2(v.x, v.y, h, l);
    g_whi[gid] = h;
    g_wlo[gid] = l;
}

// ---------------------------------------------------------------------------
// Split-bf16 tensor-core GEMM (NT) via ldmatrix + mma.sync (compute_103-legal).
// O[m,n] = sum_c A[m,c] * W[n,c].  CTA tile 128x128, BK=32, 8 warps (2m x 4n),
// warp tile 64x32, fp32 accum. 3 MMA terms: Ahi*Whi + Ahi*Wlo + Alo*Whi.
// ---------------------------------------------------------------------------
#define PITCH 80   // smem row pitch in bytes: 32 bf16 (64 B) + 16 B pad

__device__ __forceinline__ void gemm_mma_body(
    const float* __restrict__ A, int w_sel, float* __restrict__ O,
    int m0, int n0, int do_sig)
{
    __shared__ __align__(16) unsigned char sAhi[128 * PITCH];
    __shared__ __align__(16) unsigned char sAlo[128 * PITCH];
    __shared__ __align__(16) unsigned char sWhi[128 * PITCH];
    __shared__ __align__(16) unsigned char sWlo[128 * PITCH];

    const int tid  = threadIdx.x;
    const int wid  = tid >> 5;
    const int lane = tid & 31;
    const int wm   = wid & 1;        // 0..1 : 64-row half
    const int wn   = wid >> 1;       // 0..3 : 32-col quarter

    const uint32_t uAhi = smem_u32(sAhi);
    const uint32_t uAlo = smem_u32(sAlo);
    const uint32_t uWhi = smem_u32(sWhi);
    const uint32_t uWlo = smem_u32(sWlo);

    const uint32_t aOff = (uint32_t)((wm * 64 + (lane & 15)) * PITCH + (lane >> 4) * 16);
    const uint32_t bOff = (uint32_t)((wn * 32 + (lane & 7)) * PITCH + ((lane >> 3) & 1) * 16);

    float acc[4][4][4];
#pragma unroll
    for (int i = 0; i < 4; i++)
#pragma unroll
        for (int j = 0; j < 4; j++)
#pragma unroll
            for (int e = 0; e < 4; e++) acc[i][j][e] = 0.f;

    const int arow = tid >> 1;          // staging: each thread owns half a row
    const int ahalf = tid & 1;          // 16 floats

    for (int kc = 0; kc < 8; kc++) {    // K chunks of 32
        __syncthreads();
        // --- stage A chunk: fp32 -> bf16 hi/lo ---
        {
            const float* Ar = A + (size_t)(m0 + arow) * CC + kc * 32 + ahalf * 16;
            uint32_t h[8], l[8];
#pragma unroll
            for (int q = 0; q < 4; q++) {
                float4 f = *(const float4*)(Ar + q * 4);
                split2(f.x, f.y, h[q * 2],     l[q * 2]);
                split2(f.z, f.w, h[q * 2 + 1], l[q * 2 + 1]);
            }
            uint4* dh = (uint4*)(sAhi + arow * PITCH + ahalf * 32);
            uint4* dl = (uint4*)(sAlo + arow * PITCH + ahalf * 32);
            dh[0] = make_uint4(h[0], h[1], h[2], h[3]);
            dh[1] = make_uint4(h[4], h[5], h[6], h[7]);
            dl[0] = make_uint4(l[0], l[1], l[2], l[3]);
            dl[1] = make_uint4(l[4], l[5], l[6], l[7]);
        }
        // --- stage W chunk: pre-split global bf16 straight copy ---
        {
            const int base = ((w_sel * 256 + n0 + arow) * 128 + kc * 16) >> 2;  // uint4 idx
            const uint4* sh = (const uint4*)g_whi + base + ahalf * 2;
            const uint4* sl = (const uint4*)g_wlo + base + ahalf * 2;
            uint4* dh = (uint4*)(sWhi + arow * PITCH + ahalf * 32);
            uint4* dl = (uint4*)(sWlo + arow * PITCH + ahalf * 32);
            dh[0] = sh[0]; dh[1] = sh[1];
            dl[0] = sl[0]; dl[1] = sl[1];
        }
        __syncthreads();

        // --- MMA phase ---
#pragma unroll
        for (int kk = 0; kk < 2; kk++) {
            uint32_t bh[4][2], bl[4][2];
#pragma unroll
            for (int j = 0; j < 4; j++) {
                uint32_t off = bOff + (uint32_t)(j * 8 * PITCH + kk * 32);
                ldmx2(bh[j], uWhi + off);
                ldmx2(bl[j], uWlo + off);
            }
#pragma unroll
            for (int i = 0; i < 4; i++) {
                uint32_t off = aOff + (uint32_t)(i * 16 * PITCH + kk * 32);
                uint32_t ah[4], al[4];
                ldmx4(ah, uAhi + off);
                ldmx4(al, uAlo + off);
#pragma unroll
                for (int j = 0; j < 4; j++) {
                    mma16816(acc[i][j], ah, bh[j]);
                    mma16816(acc[i][j], ah, bl[j]);
                    mma16816(acc[i][j], al, bh[j]);
                }
            }
        }
    }

    // --- epilogue: fragments -> global fp32 ---
    const int r0 = m0 + wm * 64 + (lane >> 2);
    const int c0 = n0 + wn * 32 + (lane & 3) * 2;
#pragma unroll
    for (int i = 0; i < 4; i++) {
#pragma unroll
        for (int j = 0; j < 4; j++) {
            float v0 = acc[i][j][0], v1 = acc[i][j][1];
            float v2 = acc[i][j][2], v3 = acc[i][j][3];
            if (do_sig) {
                v0 = __fdividef(1.f, 1.f + __expf(-v0));
                v1 = __fdividef(1.f, 1.f + __expf(-v1));
                v2 = __fdividef(1.f, 1.f + __expf(-v2));
                v3 = __fdividef(1.f, 1.f + __expf(-v3));
            }
            float* p = O + (size_t)(r0 + i * 16) * CC + c0 + j * 8;
            *(float2*)p              = make_float2(v0, v1);
            *(float2*)(p + 8 * CC)   = make_float2(v2, v3);
        }
    }
}

__global__ __launch_bounds__(256)
void gemm_kvr_mma(const float* __restrict__ x)
{
    const int w     = blockIdx.x >> 1;        // 0:k 1:v 2:r  (x fastest -> share m-tile in L2)
    const int ntile = blockIdx.x & 1;
    float* O = (w == 0) ? g_k : (w == 1) ? g_v : g_sr;
    gemm_mma_body(x, w, O, blockIdx.y * 128, ntile * 128, w == 2);
}

__global__ __launch_bounds__(256)
void gemm_out_mma(float* __restrict__ out)
{
    gemm_mma_body(g_sr, 3, out, blockIdx.y * 128, (blockIdx.x & 1) * 128, 0);
}

// ---------------------------------------------------------------------------
// WKV pass 1: per (b, chunk) run the state recurrence from identity.
// Each thread runs TWO independent chunk chains (2-way ILP hides exp/load lat).
// ---------------------------------------------------------------------------
__global__ __launch_bounds__(256)
void wkv_pass1_kernel(const float* __restrict__ decay)
{
    const int c  = threadIdx.x;
    const int j0 = blockIdx.x * 2;        // chunks j0, j0+1
    const int b  = blockIdx.y;
    const float w = decay[c] * INV_T;
    float p0 = 0.f, q0 = 0.f, o0 = -1e38f;
    float p1 = 0.f, q1 = 0.f, o1 = -1e38f;
    int idx0 = (b * TT + j0 * LCH) * CC + c;
    int idx1 = idx0 + LCH * CC;
#pragma unroll 4
    for (int t = 0; t < LCH; t++, idx0 += CC, idx1 += CC) {
        float k0 = g_k[idx0], v0 = g_v[idx0];
        float k1 = g_k[idx1], v1 = g_v[idx1];
        float n0 = fmaxf(w + o0, k0);
        float n1 = fmaxf(w + o1, k1);
        float a0 = __expf(w + o0 - n0), b0 = __expf(k0 - n0);
        float a1 = __expf(w + o1 - n1), b1 = __expf(k1 - n1);
        p0 = a0 * p0 + b0 * v0;  q0 = a0 * q0 + b0;  o0 = n0;
        p1 = a1 * p1 + b1 * v1;  q1 = a1 * q1 + b1;  o1 = n1;
    }
    int s0 = (b * NC + j0) * CC + c;
    g_rp[s0] = p0; g_rq[s0] = q0; g_ro[s0] = o0;
    int s1 = s0 + CC;
    g_rp[s1] = p1; g_rq[s1] = q1; g_ro[s1] = o1;
}

// ---------------------------------------------------------------------------
// WKV pass 2: sequential combine across chunk summaries per (b,c).
// Batch-load 8 chunk summaries (MLP ~24) before each 8-step combine run.
// ---------------------------------------------------------------------------
__global__ __launch_bounds__(256)
void wkv_pass2_kernel(const float* __restrict__ decay)
{
    const int c = threadIdx.x;
    const int b = blockIdx.x;
    const float Lw = decay[c] * INV_T * (float)LCH;
    float p = 0.f, q = 0.f, o = -1e38f;
    for (int j0 = 0; j0 < NC; j0 += 8) {
        float rp8[8], rq8[8], ro8[8];
#pragma unroll
        for (int u = 0; u < 8; u++) {
            const int s = (b * NC + j0 + u) * CC + c;
            rp8[u] = g_rp[s]; rq8[u] = g_rq[s]; ro8[u] = g_ro[s];
        }
#pragma unroll
        for (int u = 0; u < 8; u++) {
            const int s = (b * NC + j0 + u) * CC + c;
            g_pp[s] = p; g_pq[s] = q; g_po[s] = o;
            float so = o + Lw;
            float no = fmaxf(so, ro8[u]);
            float ea = __expf(so - no);
            float eb = __expf(ro8[u] - no);
            p = ea * p + eb * rp8[u];
            q = ea * q + eb * rq8[u];
            o = no;
        }
    }
}

// ---------------------------------------------------------------------------
// WKV pass 3: replay chunk from prefix state, fuse LayerNorm + sigmoid gate.
// LN reduction batched over 8 timesteps: warp partials go to smem with NO
// barrier inside the 8-step run; one sync, batched normalize+store, one sync.
// Writes z = sigmoid(r) * LN(y) in-place into g_sr.
// ---------------------------------------------------------------------------
__global__ __launch_bounds__(256)
void wkv_pass3_kernel(const float* __restrict__ decay,
                      const float* __restrict__ first,
                      const float* __restrict__ ln_w,
                      const float* __restrict__ ln_b)
{
    __shared__ float sh_s [8][8];   // [t-sub][warp]
    __shared__ float sh_s2[8][8];
    const int c = threadIdx.x;
    const int j = blockIdx.x;
    const int b = blockIdx.y;
    const int wid  = c >> 5;
    const int lane = c & 31;

    const float w = decay[c] * INV_T;
    const float u = first[c] * INV_T;
    const float lw = ln_w[c], lb = ln_b[c];

    const int s = (b * NC + j) * CC + c;
    float p = g_pp[s], q = g_pq[s], o = g_po[s];

    int idx = (b * TT + j * LCH) * CC + c;
    for (int tb = 0; tb < LCH; tb += 8) {
        float yb[8];
        int idx2 = idx;
#pragma unroll
        for (int tt = 0; tt < 8; tt++, idx += CC) {
            float kt = g_k[idx], vt = g_v[idx];

            float no = fmaxf(o, u + kt);
            float ea = __expf(o - no);
            float eb = __expf(u + kt - no);
            float y  = __fdividef(ea * p + eb * vt, ea * q + eb);
            yb[tt] = y;

            float no2 = fmaxf(w + o, kt);
            float e2  = __expf(w + o - no2);
            float e3  = __expf(kt - no2);
            p = e2 * p + e3 * vt;
            q = e2 * q + e3;
            o = no2;

            float sv = y, sv2 = y * y;
#pragma unroll
            for (int off = 16; off; off >>= 1) {
                sv  += __shfl_xor_sync(0xffffffffu, sv,  off);
                sv2 += __shfl_xor_sync(0xffffffffu, sv2, off);
            }
            if (lane == 0) { sh_s[tt][wid] = sv; sh_s2[tt][wid] = sv2; }
        }
        __syncthreads();
#pragma unroll
        for (int tt = 0; tt < 8; tt++, idx2 += CC) {
            float mean = 0.f, msq = 0.f;
#pragma unroll
            for (int i = 0; i < 8; i++) { mean += sh_s[tt][i]; msq += sh_s2[tt][i]; }
            mean *= INV_C;
            float var = msq * INV_C - mean * mean;
            float inv = rsqrtf(var + 1e-5f);
            float z = (yb[tt] - mean) * inv * lw + lb;
            g_sr[idx2] = z * g_sr[idx2];
        }
        __syncthreads();
    }
}

// ---------------------------------------------------------------------------
extern "C" void kernel_launch(void* const* d_in, const int* in_sizes, int n_in,
                              void* d_out, int out_size)
{
    const float* x     = (const float*)d_in[0];
    const float* Wk    = (const float*)d_in[1];
    const float* Wv    = (const float*)d_in[2];
    const float* Wr    = (const float*)d_in[3];
    const float* Wo    = (const float*)d_in[4];
    const float* decay = (const float*)d_in[5];
    const float* first = (const float*)d_in[6];
    const float* ln_w  = (const float*)d_in[7];
    const float* ln_b  = (const float*)d_in[8];
    float* out = (float*)d_out;

    const int MT = (BB * TT) / 128;   // 256 m-tiles

    prep_w_kernel<<<512, 256>>>(Wk, Wv, Wr, Wo);
    gemm_kvr_mma<<<dim3(6, MT), 256>>>(x);
    wkv_pass1_kernel<<<dim3(NC / 2, BB), 256>>>(decay);
    wkv_pass2_kernel<<<BB, 256>>>(decay);
    wkv_pass3_kernel<<<dim3(NC, BB), 256>>>(decay, first, ln_w, ln_b);
    gemm_out_mma<<<dim3(2, MT), 256>>>(out);
}

// round 12
// speedup vs baseline: 1.8980x; 1.0001x over previous
#include <cuda_runtime.h>
#include <cuda_bf16.h>
#include <cstdint>

// Problem dims (fixed by the reference)
#define BB   8
#define TT   4096
#define CC   256
#define NC   64           // chunks along T for the parallel WKV scan
#define LCH  (TT / NC)    // 64 steps per chunk
#define INV_T (1.0f / 4096.0f)
#define INV_C (1.0f / 256.0f)
#define NTOT (BB * TT * CC)

// ---------------- scratch (static __device__ — no allocations allowed) -----
__device__ float g_k [NTOT];
__device__ float g_v [NTOT];
__device__ float g_sr[NTOT];           // sigmoid(r) fp32
__device__ float g_rp[BB * NC * CC];
__device__ float g_rq[BB * NC * CC];
__device__ float g_ro[BB * NC * CC];
__device__ float g_pp[BB * NC * CC];
__device__ float g_pq[BB * NC * CC];
__device__ float g_po[BB * NC * CC];

// bf16 hi/lo split activations (A operands for the GEMMs)
__device__ __align__(16) __nv_bfloat16 g_xhi[NTOT];
__device__ __align__(16) __nv_bfloat16 g_xlo[NTOT];
__device__ __align__(16) __nv_bfloat16 g_zhi[NTOT];   // z = sigmoid(r)*LN(y)
__device__ __align__(16) __nv_bfloat16 g_zlo[NTOT];

// bf16 hi/lo split weights, [w][n=256][k=256] row-major, packed as uint32 (2 bf16)
__device__ __align__(16) uint32_t g_whi[4 * 256 * 128];   // 512 KB
__device__ __align__(16) uint32_t g_wlo[4 * 256 * 128];   // 512 KB

// ---------------------------------------------------------------------------
// helpers
// ---------------------------------------------------------------------------
__device__ __forceinline__ uint32_t smem_u32(const void* p) {
    uint32_t a;
    asm("{ .reg .u64 t; cvta.to.shared.u64 t, %1; cvt.u32.u64 %0, t; }"
        : "=r"(a) : "l"(p));
    return a;
}

// split a pair of fp32 into packed bf16 hi and bf16 lo words
__device__ __forceinline__ void split2(float a, float b, uint32_t& h, uint32_t& l) {
    __nv_bfloat16 ha = __float2bfloat16_rn(a);
    __nv_bfloat16 hb = __float2bfloat16_rn(b);
    __nv_bfloat16 la = __float2bfloat16_rn(a - __bfloat162float(ha));
    __nv_bfloat16 lb = __float2bfloat16_rn(b - __bfloat162float(hb));
    h = ((uint32_t)__bfloat16_as_ushort(hb) << 16) | __bfloat16_as_ushort(ha);
    l = ((uint32_t)__bfloat16_as_ushort(lb) << 16) | __bfloat16_as_ushort(la);
}

__device__ __forceinline__ void ldmx4(uint32_t* r, uint32_t addr) {
    asm volatile("ldmatrix.sync.aligned.m8n8.x4.shared.b16 {%0,%1,%2,%3}, [%4];"
                 : "=r"(r[0]), "=r"(r[1]), "=r"(r[2]), "=r"(r[3]) : "r"(addr));
}
__device__ __forceinline__ void ldmx2(uint32_t* r, uint32_t addr) {
    asm volatile("ldmatrix.sync.aligned.m8n8.x2.shared.b16 {%0,%1}, [%2];"
                 : "=r"(r[0]), "=r"(r[1]) : "r"(addr));
}
__device__ __forceinline__ void mma16816(float* d, const uint32_t* a, const uint32_t* b) {
    asm volatile(
        "mma.sync.aligned.m16n8k16.row.col.f32.bf16.bf16.f32 "
        "{%0,%1,%2,%3}, {%4,%5,%6,%7}, {%8,%9}, {%0,%1,%2,%3};"
        : "+f"(d[0]), "+f"(d[1]), "+f"(d[2]), "+f"(d[3])
        : "r"(a[0]), "r"(a[1]), "r"(a[2]), "r"(a[3]), "r"(b[0]), "r"(b[1]));
}
__device__ __forceinline__ void cp16(uint32_t saddr, const void* g) {
    asm volatile("cp.async.cg.shared.global [%0], [%1], 16;"
                 :: "r"(saddr), "l"(g) : "memory");
}
__device__ __forceinline__ void cp_commit() {
    asm volatile("cp.async.commit_group;" ::: "memory");
}

// ---------------------------------------------------------------------------
// Weight prep: fp32 [256,256] -> bf16 hi/lo packed pairs at [w][n][k/2]
// ---------------------------------------------------------------------------
__global__ __launch_bounds__(256)
void prep_w_kernel(const float* __restrict__ Wk, const float* __restrict__ Wv,
                   const float* __restrict__ Wr, const float* __restrict__ Wo)
{
    int gid = blockIdx.x * 256 + threadIdx.x;    // 0 .. 131071 = 4*256*128
    int kp  = gid & 127;
    int n   = (gid >> 7) & 255;
    int w   = gid >> 15;
    const float* W = (w == 0) ? Wk : (w == 1) ? Wv : (w == 2) ? Wr : Wo;
    float2 v = *(const float2*)(W + n * 256 + kp * 2);
    uint32_t h, l;
    split2(v.x, v.y, h, l);
    g_whi[gid] = h;
    g_wlo[gid] = l;
}

// x fp32 -> bf16 hi/lo (one pass, so GEMM staging is a pure async copy)
__global__ __launch_bounds__(256)
void prep_x_kernel(const float* __restrict__ x)
{
    int gid = blockIdx.x * 256 + threadIdx.x;   // < NTOT/2
    float2 v = *(const float2*)(x + (size_t)gid * 2);
    uint32_t h, l;
    split2(v.x, v.y, h, l);
    ((uint32_t*)g_xhi)[gid] = h;
    ((uint32_t*)g_xlo)[gid] = l;
}

// ---------------------------------------------------------------------------
// Split-bf16 tensor-core GEMM (NT) via cp.async + ldmatrix + mma.sync.
// O[m,n] = sum_c A[m,c] * W[n,c].  CTA tile 128x128, BK=32, 8 warps (2m x 4n),
// fp32 accum, 3 MMA terms: Ahi*Whi + Ahi*Wlo + Alo*Whi.
// 2-stage cp.async double buffer: loads for kc+1 overlap MMA of kc.
// ---------------------------------------------------------------------------
#define PITCH 80                 // smem row pitch: 64 B data + 16 B pad
#define TBYTES (128 * PITCH)     // 10240 per tile
#define STG    (4 * TBYTES)      // 40960 per stage (Ahi,Alo,Whi,Wlo)
#define SMEM_BYTES (2 * STG)     // 81920

__device__ __forceinline__ void gemm_mma_body(
    const __nv_bfloat16* __restrict__ Ahi, const __nv_bfloat16* __restrict__ Alo,
    int w_sel, float* __restrict__ O, int m0, int n0, int do_sig)
{
    extern __shared__ __align__(16) unsigned char smem[];
    const uint32_t base = smem_u32(smem);

    const int tid  = threadIdx.x;
    const int wid  = tid >> 5;
    const int lane = tid & 31;
    const int wm   = wid & 1;        // 0..1 : 64-row half
    const int wn   = wid >> 1;       // 0..3 : 32-col quarter

    const uint32_t aOff = (uint32_t)((wm * 64 + (lane & 15)) * PITCH + (lane >> 4) * 16);
    const uint32_t bOff = (uint32_t)((wn * 32 + (lane & 7)) * PITCH + ((lane >> 3) & 1) * 16);

    float acc[4][4][4];
#pragma unroll
    for (int i = 0; i < 4; i++)
#pragma unroll
        for (int j = 0; j < 4; j++)
#pragma unroll
            for (int e = 0; e < 4; e++) acc[i][j][e] = 0.f;

    const int arow  = tid >> 1;      // each thread stages half a row (32 B) per tile
    const int ahalf = tid & 1;

    const __nv_bfloat16* pAh = Ahi + (size_t)(m0 + arow) * CC + ahalf * 16;
    const __nv_bfloat16* pAl = Alo + (size_t)(m0 + arow) * CC + ahalf * 16;
    const uint32_t* pWh = g_whi + (w_sel * 256 + n0 + arow) * 128 + ahalf * 8;
    const uint32_t* pWl = g_wlo + (w_sel * 256 + n0 + arow) * 128 + ahalf * 8;
    const uint32_t sOff = (uint32_t)(arow * PITCH + ahalf * 32);

    // stage loader for K-chunk kc into stage s
#define STAGE_LOAD(kc, s) do { \
        uint32_t so = base + (s) * STG + sOff; \
        cp16(so,                    pAh + (kc) * 32); \
        cp16(so + 16,               pAh + (kc) * 32 + 8); \
        cp16(so + TBYTES,           pAl + (kc) * 32); \
        cp16(so + TBYTES + 16,      pAl + (kc) * 32 + 8); \
        cp16(so + 2 * TBYTES,       pWh + (kc) * 16); \
        cp16(so + 2 * TBYTES + 16,  pWh + (kc) * 16 + 4); \
        cp16(so + 3 * TBYTES,       pWl + (kc) * 16); \
        cp16(so + 3 * TBYTES + 16,  pWl + (kc) * 16 + 4); \
        cp_commit(); \
    } while (0)

    STAGE_LOAD(0, 0);

    for (int kc = 0; kc < 8; kc++) {
        if (kc < 7) STAGE_LOAD(kc + 1, (kc + 1) & 1);
        if (kc < 7) asm volatile("cp.async.wait_group 1;" ::: "memory");
        else        asm volatile("cp.async.wait_group 0;" ::: "memory");
        __syncthreads();

        const uint32_t sb   = base + (kc & 1) * STG;
        const uint32_t uAhi = sb;
        const uint32_t uAlo = sb + TBYTES;
        const uint32_t uWhi = sb + 2 * TBYTES;
        const uint32_t uWlo = sb + 3 * TBYTES;

#pragma unroll
        for (int kk = 0; kk < 2; kk++) {
            uint32_t bh[4][2], bl[4][2];
#pragma unroll
            for (int j = 0; j < 4; j++) {
                uint32_t off = bOff + (uint32_t)(j * 8 * PITCH + kk * 32);
                ldmx2(bh[j], uWhi + off);
                ldmx2(bl[j], uWlo + off);
            }
#pragma unroll
            for (int i = 0; i < 4; i++) {
                uint32_t off = aOff + (uint32_t)(i * 16 * PITCH + kk * 32);
                uint32_t ah[4], al[4];
                ldmx4(ah, uAhi + off);
                ldmx4(al, uAlo + off);
#pragma unroll
                for (int j = 0; j < 4; j++) {
                    mma16816(acc[i][j], ah, bh[j]);
                    mma16816(acc[i][j], ah, bl[j]);
                    mma16816(acc[i][j], al, bh[j]);
                }
            }
        }
        __syncthreads();
    }
#undef STAGE_LOAD

    // --- epilogue: fragments -> global fp32 ---
    const int r0 = m0 + wm * 64 + (lane >> 2);
    const int c0 = n0 + wn * 32 + (lane & 3) * 2;
#pragma unroll
    for (int i = 0; i < 4; i++) {
#pragma unroll
        for (int j = 0; j < 4; j++) {
            float v0 = acc[i][j][0], v1 = acc[i][j][1];
            float v2 = acc[i][j][2], v3 = acc[i][j][3];
            if (do_sig) {
                v0 = __fdividef(1.f, 1.f + __expf(-v0));
                v1 = __fdividef(1.f, 1.f + __expf(-v1));
                v2 = __fdividef(1.f, 1.f + __expf(-v2));
                v3 = __fdividef(1.f, 1.f + __expf(-v3));
            }
            float* p = O + (size_t)(r0 + i * 16) * CC + c0 + j * 8;
            *(float2*)p              = make_float2(v0, v1);
            *(float2*)(p + 8 * CC)   = make_float2(v2, v3);
        }
    }
}

__global__ __launch_bounds__(256)
void gemm_kvr_mma()
{
    const int w     = blockIdx.x >> 1;        // 0:k 1:v 2:r
    const int ntile = blockIdx.x & 1;
    float* O = (w == 0) ? g_k : (w == 1) ? g_v : g_sr;
    gemm_mma_body(g_xhi, g_xlo, w, O, blockIdx.y * 128, ntile * 128, w == 2);
}

__global__ __launch_bounds__(256)
void gemm_out_mma(float* __restrict__ out)
{
    gemm_mma_body(g_zhi, g_zlo, 3, out, blockIdx.y * 128, (blockIdx.x & 1) * 128, 0);
}

// ---------------------------------------------------------------------------
// WKV pass 1: per (b, chunk) state recurrence from identity; 2 chains/thread.
// ---------------------------------------------------------------------------
__global__ __launch_bounds__(256)
void wkv_pass1_kernel(const float* __restrict__ decay)
{
    const int c  = threadIdx.x;
    const int j0 = blockIdx.x * 2;
    const int b  = blockIdx.y;
    const float w = decay[c] * INV_T;
    float p0 = 0.f, q0 = 0.f, o0 = -1e38f;
    float p1 = 0.f, q1 = 0.f, o1 = -1e38f;
    int idx0 = (b * TT + j0 * LCH) * CC + c;
    int idx1 = idx0 + LCH * CC;
#pragma unroll 4
    for (int t = 0; t < LCH; t++, idx0 += CC, idx1 += CC) {
        float k0 = g_k[idx0], v0 = g_v[idx0];
        float k1 = g_k[idx1], v1 = g_v[idx1];
        float n0 = fmaxf(w + o0, k0);
        float n1 = fmaxf(w + o1, k1);
        float a0 = __expf(w + o0 - n0), b0 = __expf(k0 - n0);
        float a1 = __expf(w + o1 - n1), b1 = __expf(k1 - n1);
        p0 = a0 * p0 + b0 * v0;  q0 = a0 * q0 + b0;  o0 = n0;
        p1 = a1 * p1 + b1 * v1;  q1 = a1 * q1 + b1;  o1 = n1;
    }
    int s0 = (b * NC + j0) * CC + c;
    g_rp[s0] = p0; g_rq[s0] = q0; g_ro[s0] = o0;
    int s1 = s0 + CC;
    g_rp[s1] = p1; g_rq[s1] = q1; g_ro[s1] = o1;
}

// ---------------------------------------------------------------------------
// WKV pass 2: sequential combine across chunk summaries per (b,c), batched 8.
// ---------------------------------------------------------------------------
__global__ __launch_bounds__(256)
void wkv_pass2_kernel(const float* __restrict__ decay)
{
    const int c = threadIdx.x;
    const int b = blockIdx.x;
    const float Lw = decay[c] * INV_T * (float)LCH;
    float p = 0.f, q = 0.f, o = -1e38f;
    for (int j0 = 0; j0 < NC; j0 += 8) {
        float rp8[8], rq8[8], ro8[8];
#pragma unroll
        for (int u = 0; u < 8; u++) {
            const int s = (b * NC + j0 + u) * CC + c;
            rp8[u] = g_rp[s]; rq8[u] = g_rq[s]; ro8[u] = g_ro[s];
        }
#pragma unroll
        for (int u = 0; u < 8; u++) {
            const int s = (b * NC + j0 + u) * CC + c;
            g_pp[s] = p; g_pq[s] = q; g_po[s] = o;
            float so = o + Lw;
            float no = fmaxf(so, ro8[u]);
            float ea = __expf(so - no);
            float eb = __expf(ro8[u] - no);
            p = ea * p + eb * rp8[u];
            q = ea * q + eb * rq8[u];
            o = no;
        }
    }
}

// ---------------------------------------------------------------------------
// WKV pass 3: replay chunk, fuse LayerNorm + sigmoid gate; write z as
// bf16 hi/lo (GEMM-ready).  LN reduction batched over 8 timesteps.
// ---------------------------------------------------------------------------
__global__ __launch_bounds__(256)
void wkv_pass3_kernel(const float* __restrict__ decay,
                      const float* __restrict__ first,
                      const float* __restrict__ ln_w,
                      const float* __restrict__ ln_b)
{
    __shared__ float sh_s [8][8];   // [t-sub][warp]
    __shared__ float sh_s2[8][8];
    const int c = threadIdx.x;
    const int j = blockIdx.x;
    const int b = blockIdx.y;
    const int wid  = c >> 5;
    const int lane = c & 31;

    const float w = decay[c] * INV_T;
    const float u = first[c] * INV_T;
    const float lw = ln_w[c], lb = ln_b[c];

    const int s = (b * NC + j) * CC + c;
    float p = g_pp[s], q = g_pq[s], o = g_po[s];

    int idx = (b * TT + j * LCH) * CC + c;
    for (int tb = 0; tb < LCH; tb += 8) {
        float yb[8];
        int idx2 = idx;
#pragma unroll
        for (int tt = 0; tt < 8; tt++, idx += CC) {
            float kt = g_k[idx], vt = g_v[idx];

            float no = fmaxf(o, u + kt);
            float ea = __expf(o - no);
            float eb = __expf(u + kt - no);
            float y  = __fdividef(ea * p + eb * vt, ea * q + eb);
            yb[tt] = y;

            float no2 = fmaxf(w + o, kt);
            float e2  = __expf(w + o - no2);
            float e3  = __expf(kt - no2);
            p = e2 * p + e3 * vt;
            q = e2 * q + e3;
            o = no2;

            float sv = y, sv2 = y * y;
#pragma unroll
            for (int off = 16; off; off >>= 1) {
                sv  += __shfl_xor_sync(0xffffffffu, sv,  off);
                sv2 += __shfl_xor_sync(0xffffffffu, sv2, off);
            }
            if (lane == 0) { sh_s[tt][wid] = sv; sh_s2[tt][wid] = sv2; }
        }
        __syncthreads();
#pragma unroll
        for (int tt = 0; tt < 8; tt++, idx2 += CC) {
            float mean = 0.f, msq = 0.f;
#pragma unroll
            for (int i = 0; i < 8; i++) { mean += sh_s[tt][i]; msq += sh_s2[tt][i]; }
            mean *= INV_C;
            float var = msq * INV_C - mean * mean;
            float inv = rsqrtf(var + 1e-5f);
            float z = (yb[tt] - mean) * inv * lw + lb;
            float zz = z * g_sr[idx2];
            __nv_bfloat16 zh = __float2bfloat16_rn(zz);
            __nv_bfloat16 zl = __float2bfloat16_rn(zz - __bfloat162float(zh));
            g_zhi[idx2] = zh;
            g_zlo[idx2] = zl;
        }
        __syncthreads();
    }
}

// ---------------------------------------------------------------------------
extern "C" void kernel_launch(void* const* d_in, const int* in_sizes, int n_in,
                              void* d_out, int out_size)
{
    const float* x     = (const float*)d_in[0];
    const float* Wk    = (const float*)d_in[1];
    const float* Wv    = (const float*)d_in[2];
    const float* Wr    = (const float*)d_in[3];
    const float* Wo    = (const float*)d_in[4];
    const float* decay = (const float*)d_in[5];
    const float* first = (const float*)d_in[6];
    const float* ln_w  = (const float*)d_in[7];
    const float* ln_b  = (const float*)d_in[8];
    float* out = (float*)d_out;

    // host-side attribute set (not a stream op; legal during capture)
    cudaFuncSetAttribute(gemm_kvr_mma, cudaFuncAttributeMaxDynamicSharedMemorySize, SMEM_BYTES);
    cudaFuncSetAttribute(gemm_out_mma, cudaFuncAttributeMaxDynamicSharedMemorySize, SMEM_BYTES);

    const int MT = (BB * TT) / 128;   // 256 m-tiles

    prep_w_kernel<<<512, 256>>>(Wk, Wv, Wr, Wo);
    prep_x_kernel<<<NTOT / 512, 256>>>(x);
    gemm_kvr_mma<<<dim3(6, MT), 256, SMEM_BYTES>>>();
    wkv_pass1_kernel<<<dim3(NC / 2, BB), 256>>>(decay);
    wkv_pass2_kernel<<<BB, 256>>>(decay);
    wkv_pass3_kernel<<<dim3(NC, BB), 256>>>(decay, first, ln_w, ln_b);
    gemm_out_mma<<<dim3(2, MT), 256, SMEM_BYTES>>>(out);
}